// round 6
// baseline (speedup 1.0000x reference)
#include <cuda_runtime.h>

#define F  16
#define C  16
#define NB 100
#define NE 101
#define NS 102          // sbin+1 range: 0..101
#define MAXN 100000
#define GRID 148        // one CTA per SM; all co-resident (spin barrier safe)
#define BS   1024
#define NW   (BS / 32)

// ---------------- device scratch (static, no allocations) ----------------
__device__ float         g_part_lo[GRID][F];
__device__ float         g_part_hi[GRID][F];
__device__ int           g_counts[F * NB];
__device__ unsigned char g_sbin[MAXN * F];    // packed sbin+1 (0..101)
__device__ int           g_bar_count;          // zero-init; self-resetting
__device__ volatile int  g_bar_gen;            // monotonic across graph replays

__device__ __forceinline__ void grid_barrier() {
    __syncthreads();
    if (threadIdx.x == 0) {
        __threadfence();
        int gen = g_bar_gen;
        if (atomicAdd(&g_bar_count, 1) == GRID - 1) {
            g_bar_count = 0;
            __threadfence();
            g_bar_gen = gen + 1;
        } else {
            while (g_bar_gen == gen) __nanosleep(64);
            __threadfence();
        }
    }
    __syncthreads();
}

// searchsorted over e[0..NE-1] (shared mem):
//   rR = #{j : e[j] <= v} (side='right'),  rL = #{j : e[j] < v} (side='left')
__device__ __forceinline__ void search2(const float* e, float v,
                                        float lo, float scale, int& rR, int& rL) {
    int g = (int)((v - lo) * scale);
    g = min(max(g, 0), NE);
    while (g < NE && e[g] <= v) ++g;
    while (g > 0 && e[g - 1] > v) --g;
    rR = g;
    while (g > 0 && e[g - 1] >= v) --g;
    rL = g;
}

__global__ void __launch_bounds__(BS, 1) k_fused(const float* __restrict__ z,
                                                 const float* __restrict__ cl,
                                                 float* __restrict__ out,
                                                 int N, float inv_div) {
    extern __shared__ float sG[];             // 104448 B union (staging/h8/G-table)
    __shared__ float se[F * NE];
    __shared__ float rlo[16][F], rhi[16][F];
    __shared__ float flo[F], fhi[F], fsc[F];
    __shared__ int   scbin[C * F];
    __shared__ float scum[F * NB];

    int t = threadIdx.x, b = blockIdx.x;
    const float INF = __int_as_float(0x7f800000);

    // ================= Phase A: min/max scan (flat float4 stream) =================
    if (b == 0)
        for (int i = t; i < F * NB; i += BS) g_counts[i] = 0;

    float4 mn4 = make_float4(INF, INF, INF, INF);
    float4 mx4 = make_float4(-INF, -INF, -INF, -INF);
    {
        int total4 = (N + C) * 4, zf4 = N * 4, stride = GRID * BS;
        for (int i = b * BS + t; i < total4; i += stride) {
            float4 v = (i < zf4) ? ((const float4*)z)[i] : ((const float4*)cl)[i - zf4];
            mn4.x = fminf(mn4.x, v.x); mx4.x = fmaxf(mx4.x, v.x);
            mn4.y = fminf(mn4.y, v.y); mx4.y = fmaxf(mx4.y, v.y);
            mn4.z = fminf(mn4.z, v.z); mx4.z = fmaxf(mx4.z, v.z);
            mn4.w = fminf(mn4.w, v.w); mx4.w = fmaxf(mx4.w, v.w);
        }
    }
#pragma unroll
    for (int o = 4; o < 32; o <<= 1) {        // combine lanes with same (lane & 3)
        mn4.x = fminf(mn4.x, __shfl_xor_sync(0xffffffffu, mn4.x, o));
        mn4.y = fminf(mn4.y, __shfl_xor_sync(0xffffffffu, mn4.y, o));
        mn4.z = fminf(mn4.z, __shfl_xor_sync(0xffffffffu, mn4.z, o));
        mn4.w = fminf(mn4.w, __shfl_xor_sync(0xffffffffu, mn4.w, o));
        mx4.x = fmaxf(mx4.x, __shfl_xor_sync(0xffffffffu, mx4.x, o));
        mx4.y = fmaxf(mx4.y, __shfl_xor_sync(0xffffffffu, mx4.y, o));
        mx4.z = fmaxf(mx4.z, __shfl_xor_sync(0xffffffffu, mx4.z, o));
        mx4.w = fmaxf(mx4.w, __shfl_xor_sync(0xffffffffu, mx4.w, o));
    }
    {
        float* swlo = sG;                      // [NW][F] staging in dynamic smem
        float* swhi = sG + NW * F;
        int w = t >> 5, lane = t & 31;
        if (lane < 4) {                        // lane g holds features 4g..4g+3
            swlo[w * F + 4 * lane + 0] = mn4.x; swhi[w * F + 4 * lane + 0] = mx4.x;
            swlo[w * F + 4 * lane + 1] = mn4.y; swhi[w * F + 4 * lane + 1] = mx4.y;
            swlo[w * F + 4 * lane + 2] = mn4.z; swhi[w * F + 4 * lane + 2] = mx4.z;
            swlo[w * F + 4 * lane + 3] = mn4.w; swhi[w * F + 4 * lane + 3] = mx4.w;
        }
        __syncthreads();
        if (t < F) {
            float lo = swlo[t], hi = swhi[t];
#pragma unroll
            for (int ww = 1; ww < NW; ww++) {
                lo = fminf(lo, swlo[ww * F + t]);
                hi = fmaxf(hi, swhi[ww * F + t]);
            }
            g_part_lo[b][t] = lo;
            g_part_hi[b][t] = hi;
        }
    }
    grid_barrier();                            // partials + count-zeroing visible

    // ======== Phase B: EVERY block redundantly reduces partials -> edges ========
    if (t < 256) {
        int f = t & 15, ch = t >> 4;           // 16 chunks x 16 features
        float lo = INF, hi = -INF;
        for (int b2 = ch; b2 < GRID; b2 += 16) {
            lo = fminf(lo, __ldcg(&g_part_lo[b2][f]));
            hi = fmaxf(hi, __ldcg(&g_part_hi[b2][f]));
        }
        rlo[ch][f] = lo; rhi[ch][f] = hi;
    }
    __syncthreads();
    if (t < F) {
        float lo = rlo[0][t], hi = rhi[0][t];
#pragma unroll
        for (int ch = 1; ch < 16; ch++) { lo = fminf(lo, rlo[ch][t]); hi = fmaxf(hi, rhi[ch][t]); }
        flo[t] = lo; fhi[t] = hi;
        fsc[t] = (hi > lo) ? (float)NB / (hi - lo) : 0.0f;
    }
    __syncthreads();
    // edges[f][j] = lo + (hi-lo)*t_j, t_j = j*0.01f in f32 (no fma contraction)
    for (int i = t; i < F * NE; i += BS) {
        int f = i / NE, j = i % NE;
        float tt = (j == NB) ? 1.0f : __fmul_rn((float)j, 0.01f);
        se[i] = __fadd_rn(flo[f], __fmul_rn(__fsub_rn(fhi[f], flo[f]), tt));
    }
    __syncthreads();
    if (t < C * F) {                           // cluster bins (all blocks, shared)
        int c = t / F, f = t % F;
        int rR, rL;
        search2(&se[f * NE], cl[c * F + f], flo[f], fsc[f], rR, rL);
        if (b == 0)                            // cluster hist contribution: once
            atomicAdd(&g_counts[f * NB + min(max(rR - 1, 0), NB - 1)], 1);
        scbin[t] = rL - 1;                     // t == c*F + f
    }
    __syncthreads();

    // ========== Phase C: bin z (one row/thread, per-warp u8 hist) ==========
    {
        unsigned char* h8 = (unsigned char*)sG;   // [NW][F*NB] = 51200 B
        for (int i = t; i < (NW * F * NB) / 4; i += BS) ((unsigned*)h8)[i] = 0u;
        __syncthreads();

        int n = b * BS + t;                       // GRID*BS = 151552 >= N
        bool valid = (n < N);
        int w = t >> 5, lane = t & 31;
        float v[F];
        if (valid) {
            const float4* zp = (const float4*)(z + (size_t)n * F);
#pragma unroll
            for (int j = 0; j < 4; j++) {
                float4 x = zp[j];
                v[4*j+0] = x.x; v[4*j+1] = x.y; v[4*j+2] = x.z; v[4*j+3] = x.w;
            }
        }
        unsigned pk[4] = {0, 0, 0, 0};
#pragma unroll
        for (int f = 0; f < F; f++) {
            int key = 127, rL = 0;
            if (valid) {
                int rR;
                search2(&se[f * NE], v[f], flo[f], fsc[f], rR, rL);
                key = min(max(rR - 1, 0), NB - 1);
            }
            unsigned mask = __match_any_sync(0xffffffffu, key);
            if (valid && lane == (__ffs(mask) - 1)) {
                int idx = w * (F * NB) + f * NB + key;
                h8[idx] = (unsigned char)(h8[idx] + __popc(mask));
            }
            pk[f >> 2] |= (unsigned)rL << (8 * (f & 3));
        }
        if (valid) {
            uint4 o; o.x = pk[0]; o.y = pk[1]; o.z = pk[2]; o.w = pk[3];
            *(uint4*)(g_sbin + (size_t)n * F) = o;
        }
        __syncthreads();
        // merge NW warp copies -> global (byte-extract, 4 bins per u32 word)
        for (int wi = t; wi < (F * NB) / 4; wi += BS) {
            unsigned s0 = 0, s1 = 0, s2 = 0, s3 = 0;
#pragma unroll
            for (int ww = 0; ww < NW; ww++) {
                unsigned x = ((const unsigned*)(h8 + ww * (F * NB)))[wi];
                s0 += x & 255u; s1 += (x >> 8) & 255u; s2 += (x >> 16) & 255u; s3 += (x >> 24);
            }
            int bb = wi * 4;
            if (s0) atomicAdd(&g_counts[bb + 0], (int)s0);
            if (s1) atomicAdd(&g_counts[bb + 1], (int)s1);
            if (s2) atomicAdd(&g_counts[bb + 2], (int)s2);
            if (s3) atomicAdd(&g_counts[bb + 3], (int)s3);
        }
    }
    grid_barrier();                            // counts + sbin visible

    // ========== Phase D: cumsum + G table + main reduction ==========
    {
        int* stage = (int*)sG;                 // reuse sG front for count staging
        for (int i = t; i < F * NB; i += BS) stage[i] = __ldcg(&g_counts[i]);
        __syncthreads();
        int w = t >> 5, lane = t & 31;
        if (w < F) {                           // warp-per-feature inclusive scan
            float carry = 0.0f;                // integer-valued -> exact in f32
#pragma unroll
            for (int ch = 0; ch < 4; ch++) {
                int idx = ch * 32 + lane;
                float v = (idx < NB) ? (float)stage[w * NB + idx] : 0.0f;
#pragma unroll
                for (int o = 1; o < 32; o <<= 1) {
                    float u = __shfl_up_sync(0xffffffffu, v, o);
                    if (lane >= o) v += u;
                }
                v += carry;
                if (idx < NB) scum[w * NB + idx] = v;
                carry = __shfl_sync(0xffffffffu, v, 31);
            }
        }
        __syncthreads();
        for (int i = t; i < F * NS * C; i += BS) {
            int c = i & (C - 1);
            int s = (i >> 4) % NS;
            int f = i / (NS * C);
            int sb = s - 1, cb = scbin[c * F + f];
            int mxb = max(sb, cb), mnb = min(sb, cb);
            float hiS = scum[f * NB + min(max(mxb, 0), NB - 1)];
            float val = (mnb <= 0) ? hiS : (hiS - scum[f * NB + (mnb - 1)]);  // exact
            float ratio = __fmul_rn(val, inv_div);
            sG[i] = __fmul_rn(ratio, ratio);
        }
        __syncthreads();

        int npairs = N * C;
        int stride = GRID * BS;
        for (int p0 = b * BS; p0 < npairs; p0 += stride) {
            int p = p0 + t;
            bool act = (p < npairs);
            int c = p & (C - 1);
            int n = min(p >> 4, N - 1);
            uint4 wv = __ldcg((const uint4*)(g_sbin + (size_t)n * F));
            unsigned ww[4] = {wv.x, wv.y, wv.z, wv.w};
            float acc = 0.0f;
#pragma unroll
            for (int f = 0; f < F; f++) {
                unsigned s = (ww[f >> 2] >> (8 * (f & 3))) & 0xFFu;
                acc += sG[(f * NS + (int)s) * C + c];
            }
            float a2 = fmaxf(acc, 1e-30f);
            float m  = a2 * rsqrtf(a2);               // fast sqrt
            float qv = __fdividef(1.0f, 1.0f + m);    // fast div
            float ssum = qv;
#pragma unroll
            for (int o = 1; o < 16; o <<= 1)
                ssum += __shfl_xor_sync(0xffffffffu, ssum, o);
            if (act) out[p] = __fdividef(qv, ssum);
        }
    }
}

// ---------------- launch ----------------
extern "C" void kernel_launch(void* const* d_in, const int* in_sizes, int n_in,
                              void* d_out, int out_size) {
    const float* z  = (const float*)d_in[0];
    const float* cl = (const float*)d_in[1];
    float* out = (float*)d_out;
    int N = in_sizes[0] / F;
    float inv_div = 1.0f / (float)(N + C);

    int smem = F * NS * C * (int)sizeof(float);   // 104448 B
    cudaFuncSetAttribute(k_fused, cudaFuncAttributeMaxDynamicSharedMemorySize, smem);
    k_fused<<<GRID, BS, smem>>>(z, cl, out, N, inv_div);
}

// round 7
// speedup vs baseline: 1.4364x; 1.4364x over previous
#include <cuda_runtime.h>

#define F  16
#define C  16
#define NB 100
#define NE 101
#define NS 102          // sbin+1 range: 0..101
#define MAXN 100000
#define GRID1 148       // k_minmax grid (fixed; ticket pattern assumes this)
#define BS1   1024

// ---------------- device scratch (static, no allocations) ----------------
__device__ float    g_part_lo[GRID1][F];
__device__ float    g_part_hi[GRID1][F];
__device__ int      g_ticket;                 // zero at load; last block resets to 0 each run
__device__ float    g_edges[F * NE];
__device__ float    g_lo[F];
__device__ float    g_scale[F];
__device__ int      g_counts[F * NB];
__device__ int      g_cbin[C * F];            // [c][f], raw bins (-1..100)
__device__ unsigned char g_sbin[MAXN * F];    // sbin+1 (0..101)

// searchsorted over e[0..NE-1]:
//   rR = #{j : e[j] <= v}  (side='right'),  rL = #{j : e[j] < v}  (side='left')
__device__ __forceinline__ void search2(const float* __restrict__ e, float v,
                                        float lo, float scale, int& rR, int& rL) {
    int g = (int)((v - lo) * scale);
    g = min(max(g, 0), NE);
    while (g < NE && e[g] <= v) ++g;
    while (g > 0 && e[g - 1] > v) --g;
    rR = g;
    while (g > 0 && e[g - 1] >= v) --g;
    rL = g;
}

__device__ __forceinline__ float4 ld_comb(const float* __restrict__ z,
                                          const float* __restrict__ cl,
                                          int i, int zf4) {
    return (i < zf4) ? ((const float4*)z)[i] : ((const float4*)cl)[i - zf4];
}
__device__ __forceinline__ void acc4(float4& mn4, float4& mx4, float4 v) {
    mn4.x = fminf(mn4.x, v.x); mx4.x = fmaxf(mx4.x, v.x);
    mn4.y = fminf(mn4.y, v.y); mx4.y = fmaxf(mx4.y, v.y);
    mn4.z = fminf(mn4.z, v.z); mx4.z = fmaxf(mx4.z, v.z);
    mn4.w = fminf(mn4.w, v.w); mx4.w = fmaxf(mx4.w, v.w);
}

// =================== K1: minmax (batched loads) + (last block) edges/cluster ===================
__global__ void __launch_bounds__(BS1) k_minmax(const float* __restrict__ z,
                                                const float* __restrict__ cl, int N) {
    int t = threadIdx.x, b = blockIdx.x;
    if (b == 0)
        for (int i = t; i < F * NB; i += BS1) g_counts[i] = 0;

    const float INF = __int_as_float(0x7f800000);
    float4 mn4 = make_float4(INF, INF, INF, INF);
    float4 mx4 = make_float4(-INF, -INF, -INF, -INF);

    // flat float4 stream; stride multiple of 4 keeps (i & 3) feature group fixed.
    int total4 = (N + C) * 4;
    int zf4    = N * 4;
    const int S = GRID1 * BS1;
    int i = b * BS1 + t;
    // batch 3 grid-stride loads before any fmin -> MLP 3x (no dependent-load loop)
    for (; i + 2 * S < total4; i += 3 * S) {
        float4 v0 = ld_comb(z, cl, i,         zf4);
        float4 v1 = ld_comb(z, cl, i + S,     zf4);
        float4 v2 = ld_comb(z, cl, i + 2 * S, zf4);
        acc4(mn4, mx4, v0); acc4(mn4, mx4, v1); acc4(mn4, mx4, v2);
    }
    for (; i < total4; i += S) acc4(mn4, mx4, ld_comb(z, cl, i, zf4));

    // combine lanes with the same group (lane & 3)
#pragma unroll
    for (int o = 4; o < 32; o <<= 1) {
        mn4.x = fminf(mn4.x, __shfl_xor_sync(0xffffffffu, mn4.x, o));
        mn4.y = fminf(mn4.y, __shfl_xor_sync(0xffffffffu, mn4.y, o));
        mn4.z = fminf(mn4.z, __shfl_xor_sync(0xffffffffu, mn4.z, o));
        mn4.w = fminf(mn4.w, __shfl_xor_sync(0xffffffffu, mn4.w, o));
        mx4.x = fmaxf(mx4.x, __shfl_xor_sync(0xffffffffu, mx4.x, o));
        mx4.y = fmaxf(mx4.y, __shfl_xor_sync(0xffffffffu, mx4.y, o));
        mx4.z = fmaxf(mx4.z, __shfl_xor_sync(0xffffffffu, mx4.z, o));
        mx4.w = fmaxf(mx4.w, __shfl_xor_sync(0xffffffffu, mx4.w, o));
    }
    __shared__ float swlo[BS1 / 32][F], swhi[BS1 / 32][F];
    int w = t >> 5, lane = t & 31;
    if (lane < 4) {          // lane g holds features 4g..4g+3
        swlo[w][4 * lane + 0] = mn4.x; swhi[w][4 * lane + 0] = mx4.x;
        swlo[w][4 * lane + 1] = mn4.y; swhi[w][4 * lane + 1] = mx4.y;
        swlo[w][4 * lane + 2] = mn4.z; swhi[w][4 * lane + 2] = mx4.z;
        swlo[w][4 * lane + 3] = mn4.w; swhi[w][4 * lane + 3] = mx4.w;
    }
    __syncthreads();
    if (t < F) {
        float lo = swlo[0][t], hi = swhi[0][t];
#pragma unroll
        for (int ww = 1; ww < BS1 / 32; ww++) {
            lo = fminf(lo, swlo[ww][t]); hi = fmaxf(hi, swhi[ww][t]);
        }
        g_part_lo[b][t] = lo;
        g_part_hi[b][t] = hi;
    }
    __threadfence();          // publish partials (and block-0 zeroing)
    __syncthreads();
    __shared__ int sLast;
    if (t == 0) sLast = (atomicAdd(&g_ticket, 1) == GRID1 - 1);
    __syncthreads();
    if (!sLast) return;
    __threadfence();          // acquire side

    // ---- last block: FULLY PARALLEL reduce (one load/thread, no dependent chains) ----
    __shared__ float s_rlo[F * GRID1], s_rhi[F * GRID1];
    for (int j = t; j < F * GRID1; j += BS1) {          // 2368 lo + 2368 hi loads, parallel
        int b2 = j >> 4, f = j & 15;
        s_rlo[f * GRID1 + b2] = __ldcg(&g_part_lo[b2][f]);
        s_rhi[f * GRID1 + b2] = __ldcg(&g_part_hi[b2][f]);
    }
    __syncthreads();
    __shared__ float flo[F], fhi[F], fsc[F];
    if (w < 2 * F) {          // warp w<16: min of feature w; warp 16+f: max of feature f
        bool isHi = (w >= F);
        int f = isHi ? (w - F) : w;
        const float* src = isHi ? s_rhi : s_rlo;
        float v = isHi ? -INF : INF;
        for (int k = lane; k < GRID1; k += 32)
            v = isHi ? fmaxf(v, src[f * GRID1 + k]) : fminf(v, src[f * GRID1 + k]);
#pragma unroll
        for (int o = 16; o > 0; o >>= 1) {
            float u = __shfl_xor_sync(0xffffffffu, v, o);
            v = isHi ? fmaxf(v, u) : fminf(v, u);
        }
        if (lane == 0) { if (isHi) fhi[f] = v; else flo[f] = v; }
    }
    __syncthreads();
    if (t < F) {
        float lo = flo[t], hi = fhi[t];
        fsc[t] = (hi > lo) ? (float)NB / (hi - lo) : 0.0f;
        g_lo[t] = lo; g_scale[t] = fsc[t];
    }
    __syncthreads();
    // edges[f][j] = lo + (hi-lo)*t_j, t_j = j*0.01f in f32 (no fma contraction)
    for (int i2 = t; i2 < F * NE; i2 += BS1) {
        int f = i2 / NE, j = i2 % NE;
        float tt = (j == NB) ? 1.0f : __fmul_rn((float)j, 0.01f);
        g_edges[i2] = __fadd_rn(flo[f], __fmul_rn(__fsub_rn(fhi[f], flo[f]), tt));
    }
    __syncthreads();
    if (t < C * F) {
        int c = t / F, f = t % F;
        int rR, rL;
        search2(&g_edges[f * NE], cl[c * F + f], flo[f], fsc[f], rR, rL);
        atomicAdd(&g_counts[f * NB + min(max(rR - 1, 0), NB - 1)], 1);
        g_cbin[t] = rL - 1;               // t == c*F + f
    }
    __threadfence();
    if (t == 0) g_ticket = 0;             // reset for next graph replay
}

// =================== K2: bin z (match-dedup per-warp u8 hist, no ATOMS) ===================
__global__ void __launch_bounds__(256) k_bin(const float* __restrict__ z, int N) {
    __shared__ float se[F * NE];
    __shared__ float slo[F], ssc[F];
    __shared__ unsigned char h8[8][F * NB];   // per-warp hist, counts <= 32 fit u8
    int t = threadIdx.x;
    for (int i = t; i < F * NE; i += 256) se[i] = g_edges[i];
    if (t < F) { slo[t] = g_lo[t]; ssc[t] = g_scale[t]; }
    for (int i = t; i < (8 * F * NB) / 4; i += 256) ((unsigned*)h8)[i] = 0u;
    __syncthreads();

    int n = blockIdx.x * 256 + t;                // one row per lane (grid covers N)
    bool valid = (n < N);
    int w = t >> 5, lane = t & 31;
    float v[F];
    if (valid) {
        const float4* zp = (const float4*)(z + (size_t)n * F);
#pragma unroll
        for (int j = 0; j < 4; j++) {
            float4 x = zp[j];
            v[4*j+0] = x.x; v[4*j+1] = x.y; v[4*j+2] = x.z; v[4*j+3] = x.w;
        }
    }
    unsigned pk[4] = {0, 0, 0, 0};
#pragma unroll
    for (int f = 0; f < F; f++) {
        int key = 127, rL = 0;
        if (valid) {
            int rR;
            search2(&se[f * NE], v[f], slo[f], ssc[f], rR, rL);
            key = min(max(rR - 1, 0), NB - 1);
        }
        unsigned mask = __match_any_sync(0xffffffffu, key);
        if (valid && lane == (__ffs(mask) - 1)) {
            int idx = f * NB + key;
            h8[w][idx] = (unsigned char)(h8[w][idx] + __popc(mask));
        }
        pk[f >> 2] |= (unsigned)rL << (8 * (f & 3));
    }
    if (valid) {
        uint4 o; o.x = pk[0]; o.y = pk[1]; o.z = pk[2]; o.w = pk[3];
        *(uint4*)(g_sbin + (size_t)n * F) = o;
    }
    __syncthreads();
    // merge 8 warp copies -> global (byte-extract, 4 bins per u32 word)
    for (int wi = t; wi < (F * NB) / 4; wi += 256) {
        unsigned s0 = 0, s1 = 0, s2 = 0, s3 = 0;
#pragma unroll
        for (int ww = 0; ww < 8; ww++) {
            unsigned x = ((const unsigned*)h8[ww])[wi];
            s0 += x & 255u; s1 += (x >> 8) & 255u; s2 += (x >> 16) & 255u; s3 += (x >> 24);
        }
        int b = wi * 4;
        if (s0) atomicAdd(&g_counts[b + 0], (int)s0);
        if (s1) atomicAdd(&g_counts[b + 1], (int)s1);
        if (s2) atomicAdd(&g_counts[b + 2], (int)s2);
        if (s3) atomicAdd(&g_counts[b + 3], (int)s3);
    }
}

// =================== K3: cum + G build (per block) + main reduction ===================
__global__ void __launch_bounds__(1024) k_main(float* __restrict__ out, int N, float inv_div) {
    extern __shared__ float sG[];             // F*NS*C floats (104448 B)
    __shared__ float scum[F * NB];
    __shared__ int   scbin[C * F];
    int t = threadIdx.x;
    const int bs = 1024;

    int* stage = (int*)sG;                    // reuse sG front as count staging
    for (int i = t; i < F * NB; i += bs) stage[i] = g_counts[i];
    if (t < C * F) scbin[t] = g_cbin[t];
    __syncthreads();
    int w = t >> 5, lane = t & 31;
    if (w < F) {                              // warp-per-feature inclusive scan
        float carry = 0.0f;                   // integer-valued -> exact in f32
#pragma unroll
        for (int ch = 0; ch < 4; ch++) {
            int idx = ch * 32 + lane;
            float v = (idx < NB) ? (float)stage[w * NB + idx] : 0.0f;
#pragma unroll
            for (int o = 1; o < 32; o <<= 1) {
                float u = __shfl_up_sync(0xffffffffu, v, o);
                if (lane >= o) v += u;
            }
            v += carry;
            if (idx < NB) scum[w * NB + idx] = v;
            carry = __shfl_sync(0xffffffffu, v, 31);
        }
    }
    __syncthreads();
    for (int i = t; i < F * NS * C; i += bs) {
        int c = i & (C - 1);
        int s = (i >> 4) % NS;                // const-div -> mul/shift
        int f = i / (NS * C);
        int sb = s - 1, cb = scbin[c * F + f];
        int mxb = max(sb, cb), mnb = min(sb, cb);
        float hiS = scum[f * NB + min(max(mxb, 0), NB - 1)];
        float val = (mnb <= 0) ? hiS : (hiS - scum[f * NB + (mnb - 1)]);  // exact ints
        float ratio = __fmul_rn(val, inv_div);
        sG[i] = __fmul_rn(ratio, ratio);
    }
    __syncthreads();

    int npairs = N * C;
    int stride = gridDim.x * bs;
    for (int p0 = blockIdx.x * bs; p0 < npairs; p0 += stride) {
        int p = p0 + t;
        bool act = (p < npairs);
        int c = p & (C - 1);
        int n = min(p >> 4, N - 1);
        uint4 wv = *(const uint4*)(g_sbin + (size_t)n * F);
        unsigned ww[4] = {wv.x, wv.y, wv.z, wv.w};
        float acc = 0.0f;
#pragma unroll
        for (int f = 0; f < F; f++) {
            unsigned s = (ww[f >> 2] >> (8 * (f & 3))) & 0xFFu;
            acc += sG[(f * NS + (int)s) * C + c];
        }
        float a2 = fmaxf(acc, 1e-30f);
        float m  = a2 * rsqrtf(a2);               // fast sqrt (MUFU.RSQ)
        float qv = __fdividef(1.0f, 1.0f + m);    // fast div
        float ssum = qv;
#pragma unroll
        for (int o = 1; o < 16; o <<= 1)
            ssum += __shfl_xor_sync(0xffffffffu, ssum, o);
        if (act) out[p] = __fdividef(qv, ssum);
    }
}

// ---------------- launch ----------------
extern "C" void kernel_launch(void* const* d_in, const int* in_sizes, int n_in,
                              void* d_out, int out_size) {
    const float* z  = (const float*)d_in[0];
    const float* cl = (const float*)d_in[1];
    float* out = (float*)d_out;
    int N = in_sizes[0] / F;
    float inv_div = 1.0f / (float)(N + C);

    cudaFuncSetAttribute(k_main, cudaFuncAttributeMaxDynamicSharedMemorySize,
                         F * NS * C * (int)sizeof(float));

    k_minmax<<<GRID1, BS1>>>(z, cl, N);
    k_bin<<<(N + 255) / 256, 256>>>(z, N);
    k_main<<<148, 1024, F * NS * C * (int)sizeof(float)>>>(out, N, inv_div);
}